// round 4
// baseline (speedup 1.0000x reference)
#include <cuda_runtime.h>
#include <math.h>
#include <stdint.h>

// ---------------- problem constants ----------------
#define BB 256      // batch
#define TT 128      // timesteps
#define FF 784      // input features
#define HH 1024     // hidden
#define CC 10       // classes
#define M1 (BB*TT)  // 32768 rows for the time-parallel GEMMs
#define BN_EPS 1e-3f

// ---------------- scratch (device globals) ----------------
__device__ float g_feat[(size_t)M1 * HH];
__device__ float g_zx  [(size_t)M1 * 4 * HH];
__device__ float g_hseq[(size_t)M1 * HH];
__device__ float g_c   [(size_t)BB * HH];

// ---------------- helpers ----------------
__device__ __forceinline__ uint32_t f2tf(float f) {
    uint32_t u;
    asm("cvt.rna.tf32.f32 %0, %1;" : "=r"(u) : "f"(f));
    return u;
}

__device__ __forceinline__ void cp16(void* dst, const void* src) {
    uint32_t d = (uint32_t)__cvta_generic_to_shared(dst);
    asm volatile("cp.async.cg.shared.global [%0], [%1], 16;" :: "r"(d), "l"(src));
}
#define CP_COMMIT asm volatile("cp.async.commit_group;")
#define CP_WAIT1  asm volatile("cp.async.wait_group 1;")
#define CP_WAIT0  asm volatile("cp.async.wait_group 0;")

__device__ __forceinline__ void mma_tf32(float* d, const uint32_t* a, const uint32_t* b) {
    asm volatile(
        "mma.sync.aligned.m16n8k8.row.col.f32.tf32.tf32.f32 "
        "{%0,%1,%2,%3}, {%4,%5,%6,%7}, {%8,%9}, {%0,%1,%2,%3};"
        : "+f"(d[0]), "+f"(d[1]), "+f"(d[2]), "+f"(d[3])
        : "r"(a[0]), "r"(a[1]), "r"(a[2]), "r"(a[3]),
          "r"(b[0]), "r"(b[1]));
}

__global__ void zero_kernel(float* __restrict__ p, int n) {
    int i = blockIdx.x * blockDim.x + threadIdx.x;
    if (i < n) p[i] = 0.0f;
}

// ---------------- tf32 tensor-core GEMM (time-parallel big GEMMs) ------------
// C[M,N] = epilogue(A[M,K] @ B[K,N])
// EPI 1: feat epilogue (tanh,BN,tanh)   2: +bias
template<int BM, int BN, int BK, int WM, int WN, int EPI>
__global__ void __launch_bounds__((BM/WM)*(BN/WN)*32)
gemm_tf32(const float* __restrict__ A, const float* __restrict__ B,
          float* __restrict__ C, int M, int N, int K,
          const float* __restrict__ p0, const float* __restrict__ p1,
          const float* __restrict__ p2, const float* __restrict__ p3,
          const float* __restrict__ p4)
{
    constexpr int WARPS_N = BN / WN;
    constexpr int THREADS = (BM/WM) * (BN/WN) * 32;
    constexpr int MI = WM / 16;
    constexpr int NI = WN / 8;
    constexpr int KS = BK / 8;
    constexpr int AST = BK + 4;
    constexpr int BST = BN + 8;
    constexpr int AQ = BM * BK / 4;
    constexpr int BQ = BK * BN / 4;

    __shared__ float As[2][BM * AST];
    __shared__ float Bs[2][BK * BST];

    const int tid  = threadIdx.x;
    const int lane = tid & 31;
    const int warp = tid >> 5;
    const int wm   = (warp / WARPS_N) * WM;
    const int wn   = (warp % WARPS_N) * WN;
    const int row0 = blockIdx.y * BM;
    const int col0 = blockIdx.x * BN;

    float acc[MI][NI][4];
#pragma unroll
    for (int mi = 0; mi < MI; mi++)
#pragma unroll
        for (int ni = 0; ni < NI; ni++)
#pragma unroll
            for (int r = 0; r < 4; r++) acc[mi][ni][r] = 0.0f;

    const int KT = K / BK;

#pragma unroll
    for (int q = tid; q < AQ; q += THREADS) {
        int r = q / (BK/4), c = (q % (BK/4)) * 4;
        cp16(&As[0][r * AST + c], A + (size_t)(row0 + r) * K + c);
    }
#pragma unroll
    for (int q = tid; q < BQ; q += THREADS) {
        int r = q / (BN/4), c = (q % (BN/4)) * 4;
        cp16(&Bs[0][r * BST + c], B + (size_t)r * N + col0 + c);
    }
    CP_COMMIT;

#pragma unroll 1
    for (int kt = 0; kt < KT; kt++) {
        const int cur = kt & 1;
        if (kt + 1 < KT) {
            const int k0 = (kt + 1) * BK;
            const int nxt = cur ^ 1;
#pragma unroll
            for (int q = tid; q < AQ; q += THREADS) {
                int r = q / (BK/4), c = (q % (BK/4)) * 4;
                cp16(&As[nxt][r * AST + c], A + (size_t)(row0 + r) * K + k0 + c);
            }
#pragma unroll
            for (int q = tid; q < BQ; q += THREADS) {
                int r = q / (BN/4), c = (q % (BN/4)) * 4;
                cp16(&Bs[nxt][r * BST + c], B + (size_t)(k0 + r) * N + col0 + c);
            }
            CP_COMMIT;
            CP_WAIT1;
        } else {
            CP_WAIT0;
        }
        __syncthreads();

#pragma unroll
        for (int ks = 0; ks < KS; ks++) {
            uint32_t afr[MI][4];
            uint32_t bfr[NI][2];
            const int ar = lane >> 2;
            const int ac = ks * 8 + (lane & 3);
#pragma unroll
            for (int mi = 0; mi < MI; mi++) {
                const float* base = &As[cur][(wm + mi * 16 + ar) * AST + ac];
                afr[mi][0] = f2tf(base[0]);
                afr[mi][1] = f2tf(base[8 * AST]);
                afr[mi][2] = f2tf(base[4]);
                afr[mi][3] = f2tf(base[8 * AST + 4]);
            }
            const int bk = ks * 8 + (lane & 3);
            const int bn = lane >> 2;
#pragma unroll
            for (int ni = 0; ni < NI; ni++) {
                const float* base = &Bs[cur][bk * BST + wn + ni * 8 + bn];
                bfr[ni][0] = f2tf(base[0]);
                bfr[ni][1] = f2tf(base[4 * BST]);
            }
#pragma unroll
            for (int mi = 0; mi < MI; mi++)
#pragma unroll
                for (int ni = 0; ni < NI; ni++)
                    mma_tf32(acc[mi][ni], afr[mi], bfr[ni]);
        }
        __syncthreads();
    }

#pragma unroll
    for (int mi = 0; mi < MI; mi++) {
#pragma unroll
        for (int ni = 0; ni < NI; ni++) {
            const int r0 = row0 + wm + mi * 16 + (lane >> 2);
            const int c0 = col0 + wn + ni * 8 + 2 * (lane & 3);
#pragma unroll
            for (int half = 0; half < 2; half++) {
                const int rr = r0 + half * 8;
#pragma unroll
                for (int e = 0; e < 2; e++) {
                    const int nn = c0 + e;
                    float v = acc[mi][ni][half * 2 + e];
                    if (EPI == 1) {
                        v = tanhf(v + p0[nn]);
                        v = (v - p3[nn]) * rsqrtf(p4[nn] + BN_EPS) * p1[nn] + p2[nn];
                        v = tanhf(v);
                    } else if (EPI == 2) {
                        v += p0[nn];
                    }
                    C[(size_t)rr * N + nn] = v;
                }
            }
        }
    }
}

// ---------------- fused recurrent step: Zh GEMM + LSTM gates -----------------
// Grid: x = j-tile (HH/32 = 32), y = m-tile (BB/64 = 4). 256 threads (8 warps,
// 2 warp-rows x 4 warp-cols, WM=32, WN=32). Each CTA computes rows
// [row0,row0+64) x gate columns {g*HH + j0..j0+32 : g=0..3}, then applies the
// full gate nonlinearity with Zx and the cell state, writing h and c.
#define FBM 64
#define FBK 16
#define FBN 128              // 4 gate slabs x 32 j
#define FAST (FBK + 4)
#define FBST (FBN + 8)
#define FEST (FBN + 4)       // epilogue smem stride

struct FusedSmem {
    union {
        struct {
            float As[2][FBM * FAST];
            float Bs[2][FBK * FBST];
        } mm;
        float ep[FBM * FEST];
    };
};

__global__ void __launch_bounds__(256)
lstm_step_kernel(const float* __restrict__ hprev,   // (BB, HH) or ignored
                 const float* __restrict__ Wr,      // (HH, 4*HH)
                 const float* __restrict__ Zx,      // (BB*TT, 4*HH)
                 float* __restrict__ cst,           // (BB, HH)
                 float* __restrict__ hout,          // (BB, HH) slice of hseq
                 const float* __restrict__ pi, const float* __restrict__ pf,
                 const float* __restrict__ po, int t, int skip_gemm)
{
    __shared__ FusedSmem S;

    const int tid  = threadIdx.x;
    const int lane = tid & 31;
    const int warp = tid >> 5;
    const int wm   = (warp >> 2) * 32;          // warp row: 0 or 32
    const int wn   = (warp & 3) * 32;           // warp col: one gate slab
    const int row0 = blockIdx.y * FBM;
    const int j0   = blockIdx.x * 32;

    float acc[2][4][4];
#pragma unroll
    for (int mi = 0; mi < 2; mi++)
#pragma unroll
        for (int ni = 0; ni < 4; ni++)
#pragma unroll
            for (int r = 0; r < 4; r++) acc[mi][ni][r] = 0.0f;

    if (!skip_gemm) {
        constexpr int AQ = FBM * FBK / 4;   // 256 -> 1/thread
        constexpr int BQ = FBK * FBN / 4;   // 512 -> 2/thread
        constexpr int KT = HH / FBK;        // 64

        // prologue
        {
            int q = tid;
            int r = q / (FBK/4), c = (q % (FBK/4)) * 4;
            cp16(&S.mm.As[0][r * FAST + c], hprev + (size_t)(row0 + r) * HH + c);
#pragma unroll
            for (int qq = tid; qq < BQ; qq += 256) {
                int br = qq / 32, ci = qq % 32;
                int g = ci >> 3, jj = (ci & 7) * 4;
                cp16(&S.mm.Bs[0][br * FBST + g * 32 + jj],
                     Wr + (size_t)br * (4*HH) + g * HH + j0 + jj);
            }
            CP_COMMIT;
        }

#pragma unroll 1
        for (int kt = 0; kt < KT; kt++) {
            const int cur = kt & 1;
            if (kt + 1 < KT) {
                const int k0 = (kt + 1) * FBK;
                const int nxt = cur ^ 1;
                int q = tid;
                int r = q / (FBK/4), c = (q % (FBK/4)) * 4;
                cp16(&S.mm.As[nxt][r * FAST + c],
                     hprev + (size_t)(row0 + r) * HH + k0 + c);
#pragma unroll
                for (int qq = tid; qq < BQ; qq += 256) {
                    int br = qq / 32, ci = qq % 32;
                    int g = ci >> 3, jj = (ci & 7) * 4;
                    cp16(&S.mm.Bs[nxt][br * FBST + g * 32 + jj],
                         Wr + (size_t)(k0 + br) * (4*HH) + g * HH + j0 + jj);
                }
                CP_COMMIT;
                CP_WAIT1;
            } else {
                CP_WAIT0;
            }
            __syncthreads();

#pragma unroll
            for (int ks = 0; ks < FBK/8; ks++) {
                uint32_t afr[2][4];
                uint32_t bfr[4][2];
                const int ar = lane >> 2;
                const int ac = ks * 8 + (lane & 3);
#pragma unroll
                for (int mi = 0; mi < 2; mi++) {
                    const float* base = &S.mm.As[cur][(wm + mi * 16 + ar) * FAST + ac];
                    afr[mi][0] = f2tf(base[0]);
                    afr[mi][1] = f2tf(base[8 * FAST]);
                    afr[mi][2] = f2tf(base[4]);
                    afr[mi][3] = f2tf(base[8 * FAST + 4]);
                }
                const int bk = ks * 8 + (lane & 3);
                const int bn = lane >> 2;
#pragma unroll
                for (int ni = 0; ni < 4; ni++) {
                    const float* base = &S.mm.Bs[cur][bk * FBST + wn + ni * 8 + bn];
                    bfr[ni][0] = f2tf(base[0]);
                    bfr[ni][1] = f2tf(base[4 * FBST]);
                }
#pragma unroll
                for (int mi = 0; mi < 2; mi++)
#pragma unroll
                    for (int ni = 0; ni < 4; ni++)
                        mma_tf32(acc[mi][ni], afr[mi], bfr[ni]);
            }
            __syncthreads();
        }
    } else {
        __syncthreads();
    }

    // ---- dump Zh accumulators to smem epilogue buffer ----
#pragma unroll
    for (int mi = 0; mi < 2; mi++) {
#pragma unroll
        for (int ni = 0; ni < 4; ni++) {
            const int r0 = wm + mi * 16 + (lane >> 2);
            const int c0 = wn + ni * 8 + 2 * (lane & 3);
#pragma unroll
            for (int half = 0; half < 2; half++) {
                S.ep[(r0 + half * 8) * FEST + c0]     = acc[mi][ni][half * 2];
                S.ep[(r0 + half * 8) * FEST + c0 + 1] = acc[mi][ni][half * 2 + 1];
            }
        }
    }
    __syncthreads();

    // ---- gates: each thread handles 8 (m, j) pairs ----
    const int j  = tid & 31;       // 0..31
    const int jg = j0 + j;
    const float pij = pi[jg], pfj = pf[jg], poj = po[jg];

#pragma unroll
    for (int s = 0; s < 8; s++) {
        const int m = s * 8 + (tid >> 5);      // 0..63
        const int b = row0 + m;
        const size_t zr = ((size_t)b * TT + t) * (4 * HH);

        float zi = S.ep[m * FEST +       j] + Zx[zr + 0*HH + jg];
        float zf = S.ep[m * FEST +  32 + j] + Zx[zr + 1*HH + jg];
        float zc = S.ep[m * FEST +  64 + j] + Zx[zr + 2*HH + jg];
        float zo = S.ep[m * FEST +  96 + j] + Zx[zr + 3*HH + jg];

        float cc = cst[(size_t)b * HH + jg];
        float ig = 1.0f / (1.0f + expf(-(zi + cc * pij)));
        float fg = 1.0f / (1.0f + expf(-(zf + cc * pfj)));
        float cn = fg * cc + ig * tanhf(zc);
        float og = 1.0f / (1.0f + expf(-(zo + cn * poj)));

        cst[(size_t)b * HH + jg]  = cn;
        hout[(size_t)b * HH + jg] = og * tanhf(cn);
    }
}

// ---------------- final BN -> tanh -> Dense(H,10) ----------------------------
__global__ void logits_kernel(const float* __restrict__ hseq,
                              const float* __restrict__ g2, const float* __restrict__ b2,
                              const float* __restrict__ m2, const float* __restrict__ v2,
                              const float* __restrict__ Wout, float* __restrict__ out)
{
    int row = blockIdx.x;            // = t*BB + b (hseq is (T,B,H))
    int t = row / BB, b = row % BB;
    int tid = threadIdx.x;

    float a[CC];
#pragma unroll
    for (int c2 = 0; c2 < CC; c2++) a[c2] = 0.0f;

    float4 hv = *(const float4*)(hseq + (size_t)row * HH + tid * 4);
    float4 gv = *(const float4*)(g2 + tid * 4);
    float4 bv = *(const float4*)(b2 + tid * 4);
    float4 mv = *(const float4*)(m2 + tid * 4);
    float4 vv = *(const float4*)(v2 + tid * 4);

    float h4[4] = {hv.x, hv.y, hv.z, hv.w};
    float G4[4] = {gv.x, gv.y, gv.z, gv.w};
    float B4[4] = {bv.x, bv.y, bv.z, bv.w};
    float M4[4] = {mv.x, mv.y, mv.z, mv.w};
    float V4[4] = {vv.x, vv.y, vv.z, vv.w};

#pragma unroll
    for (int s = 0; s < 4; s++) {
        int k = tid * 4 + s;
        float y = tanhf((h4[s] - M4[s]) * rsqrtf(V4[s] + BN_EPS) * G4[s] + B4[s]);
        const float* wr = Wout + (size_t)k * CC;
#pragma unroll
        for (int c2 = 0; c2 < CC; c2++)
            a[c2] = fmaf(y, wr[c2], a[c2]);
    }

#pragma unroll
    for (int off = 16; off > 0; off >>= 1)
#pragma unroll
        for (int c2 = 0; c2 < CC; c2++)
            a[c2] += __shfl_down_sync(0xffffffffu, a[c2], off);

    __shared__ float sacc[CC];
    if (tid < CC) sacc[tid] = 0.0f;
    __syncthreads();
    if ((tid & 31) == 0)
#pragma unroll
        for (int c2 = 0; c2 < CC; c2++) atomicAdd(&sacc[c2], a[c2]);
    __syncthreads();
    if (tid < CC)
        out[((size_t)b * TT + t) * CC + tid] = sacc[tid];
}

// ---------------- launcher ----------------------------------------------------
extern "C" void kernel_launch(void* const* d_in, const int* in_sizes, int n_in,
                              void* d_out, int out_size)
{
    const float* x      = (const float*)d_in[0];
    const float* W_fe   = (const float*)d_in[1];
    const float* b_fe   = (const float*)d_in[2];
    const float* gamma1 = (const float*)d_in[3];
    const float* beta1  = (const float*)d_in[4];
    const float* mean1  = (const float*)d_in[5];
    const float* var1   = (const float*)d_in[6];
    const float* Wg     = (const float*)d_in[7];   // kernel (H, 4H)
    const float* Wr     = (const float*)d_in[8];   // rec_kernel (H, 4H)
    const float* bias   = (const float*)d_in[9];
    const float* pi     = (const float*)d_in[10];
    const float* pf     = (const float*)d_in[11];
    const float* po     = (const float*)d_in[12];
    const float* gamma2 = (const float*)d_in[13];
    const float* beta2  = (const float*)d_in[14];
    const float* mean2  = (const float*)d_in[15];
    const float* var2   = (const float*)d_in[16];
    const float* W_out  = (const float*)d_in[17];
    float* out = (float*)d_out;

    float *feat, *zx, *hseq, *cbuf;
    cudaGetSymbolAddress((void**)&feat, g_feat);
    cudaGetSymbolAddress((void**)&zx,   g_zx);
    cudaGetSymbolAddress((void**)&hseq, g_hseq);
    cudaGetSymbolAddress((void**)&cbuf, g_c);

    // zero cell state
    zero_kernel<<<(BB*HH + 255)/256, 256>>>(cbuf, BB*HH);

    // 1) feat = tanh(BN(tanh(x @ W_fe + b_fe)))   [32768 x 1024, K=784]
    {
        dim3 grid(HH/128, M1/128);
        gemm_tf32<128,128,16,32,64,1><<<grid, 256>>>(
            x, W_fe, feat, M1, HH, FF, b_fe, gamma1, beta1, mean1, var1);
    }
    // 2) Zx = feat @ kernel + bias                [32768 x 4096, K=1024]
    {
        dim3 grid(4*HH/128, M1/128);
        gemm_tf32<128,128,16,32,64,2><<<grid, 256>>>(
            feat, Wg, zx, M1, 4*HH, HH, bias, nullptr, nullptr, nullptr, nullptr);
    }
    // 3) recurrence: one fused kernel per step
    {
        dim3 gstep(HH/32, BB/FBM);   // 32 x 4 = 128 CTAs
        lstm_step_kernel<<<gstep, 256>>>(nullptr, Wr, zx, cbuf,
                                         hseq, pi, pf, po, 0, 1);
        for (int t = 1; t < TT; t++) {
            lstm_step_kernel<<<gstep, 256>>>(hseq + (size_t)(t-1)*BB*HH, Wr, zx,
                                             cbuf, hseq + (size_t)t*BB*HH,
                                             pi, pf, po, t, 0);
        }
    }
    // 4) out = tanh(BN(hseq)) @ W_out             [32768 x 10]
    logits_kernel<<<M1, 256>>>(hseq, gamma2, beta2, mean2, var2, W_out, out);
}

// round 5
// speedup vs baseline: 1.0376x; 1.0376x over previous
#include <cuda_runtime.h>
#include <math.h>
#include <stdint.h>

// ---------------- problem constants ----------------
#define BB 256      // batch
#define TT 128      // timesteps
#define FF 784      // input features
#define HH 1024     // hidden
#define CC 10       // classes
#define M1 (BB*TT)  // 32768 rows for the time-parallel GEMMs
#define BN_EPS 1e-3f

// ---------------- scratch (device globals) ----------------
__device__ float g_feat[(size_t)M1 * HH];
__device__ float g_zx  [(size_t)M1 * 4 * HH];
__device__ float g_hseq[(size_t)M1 * HH];
__device__ float g_c   [(size_t)BB * HH];
__device__ volatile unsigned g_bar;          // grid barrier counter

// ---------------- helpers ----------------
__device__ __forceinline__ uint32_t f2tf(float f) {
    uint32_t u;
    asm("cvt.rna.tf32.f32 %0, %1;" : "=r"(u) : "f"(f));
    return u;
}

__device__ __forceinline__ void cp16(void* dst, const void* src) {
    uint32_t d = (uint32_t)__cvta_generic_to_shared(dst);
    asm volatile("cp.async.cg.shared.global [%0], [%1], 16;" :: "r"(d), "l"(src));
}
#define CP_COMMIT asm volatile("cp.async.commit_group;")
#define CP_WAITN(n) asm volatile("cp.async.wait_group %0;" :: "n"(n))

__device__ __forceinline__ void mma_tf32(float* d, const uint32_t* a, const uint32_t* b) {
    asm volatile(
        "mma.sync.aligned.m16n8k8.row.col.f32.tf32.tf32.f32 "
        "{%0,%1,%2,%3}, {%4,%5,%6,%7}, {%8,%9}, {%0,%1,%2,%3};"
        : "+f"(d[0]), "+f"(d[1]), "+f"(d[2]), "+f"(d[3])
        : "r"(a[0]), "r"(a[1]), "r"(a[2]), "r"(a[3]),
          "r"(b[0]), "r"(b[1]));
}

__global__ void init_kernel(float* __restrict__ c, int n) {
    int i = blockIdx.x * blockDim.x + threadIdx.x;
    if (i < n) c[i] = 0.0f;
    if (i == 0) g_bar = 0u;
}

// ---------------- tf32 tensor-core GEMM (time-parallel big GEMMs) ------------
// C[M,N] = epilogue(A[M,K] @ B[K,N])
// EPI 1: feat epilogue (tanh,BN,tanh)   2: +bias
template<int BM, int BN, int BK, int WM, int WN, int EPI>
__global__ void __launch_bounds__((BM/WM)*(BN/WN)*32)
gemm_tf32(const float* __restrict__ A, const float* __restrict__ B,
          float* __restrict__ C, int M, int N, int K,
          const float* __restrict__ p0, const float* __restrict__ p1,
          const float* __restrict__ p2, const float* __restrict__ p3,
          const float* __restrict__ p4)
{
    constexpr int WARPS_N = BN / WN;
    constexpr int THREADS = (BM/WM) * (BN/WN) * 32;
    constexpr int MI = WM / 16;
    constexpr int NI = WN / 8;
    constexpr int KS = BK / 8;
    constexpr int AST = BK + 4;
    constexpr int BST = BN + 8;
    constexpr int AQ = BM * BK / 4;
    constexpr int BQ = BK * BN / 4;

    __shared__ float As[2][BM * AST];
    __shared__ float Bs[2][BK * BST];

    const int tid  = threadIdx.x;
    const int lane = tid & 31;
    const int warp = tid >> 5;
    const int wm   = (warp / WARPS_N) * WM;
    const int wn   = (warp % WARPS_N) * WN;
    const int row0 = blockIdx.y * BM;
    const int col0 = blockIdx.x * BN;

    float acc[MI][NI][4];
#pragma unroll
    for (int mi = 0; mi < MI; mi++)
#pragma unroll
        for (int ni = 0; ni < NI; ni++)
#pragma unroll
            for (int r = 0; r < 4; r++) acc[mi][ni][r] = 0.0f;

    const int KT = K / BK;

#pragma unroll
    for (int q = tid; q < AQ; q += THREADS) {
        int r = q / (BK/4), c = (q % (BK/4)) * 4;
        cp16(&As[0][r * AST + c], A + (size_t)(row0 + r) * K + c);
    }
#pragma unroll
    for (int q = tid; q < BQ; q += THREADS) {
        int r = q / (BN/4), c = (q % (BN/4)) * 4;
        cp16(&Bs[0][r * BST + c], B + (size_t)r * N + col0 + c);
    }
    CP_COMMIT;

#pragma unroll 1
    for (int kt = 0; kt < KT; kt++) {
        const int cur = kt & 1;
        if (kt + 1 < KT) {
            const int k0 = (kt + 1) * BK;
            const int nxt = cur ^ 1;
#pragma unroll
            for (int q = tid; q < AQ; q += THREADS) {
                int r = q / (BK/4), c = (q % (BK/4)) * 4;
                cp16(&As[nxt][r * AST + c], A + (size_t)(row0 + r) * K + k0 + c);
            }
#pragma unroll
            for (int q = tid; q < BQ; q += THREADS) {
                int r = q / (BN/4), c = (q % (BN/4)) * 4;
                cp16(&Bs[nxt][r * BST + c], B + (size_t)(k0 + r) * N + col0 + c);
            }
            CP_COMMIT;
            CP_WAITN(1);
        } else {
            CP_WAITN(0);
        }
        __syncthreads();

#pragma unroll
        for (int ks = 0; ks < KS; ks++) {
            uint32_t afr[MI][4];
            uint32_t bfr[NI][2];
            const int ar = lane >> 2;
            const int ac = ks * 8 + (lane & 3);
#pragma unroll
            for (int mi = 0; mi < MI; mi++) {
                const float* base = &As[cur][(wm + mi * 16 + ar) * AST + ac];
                afr[mi][0] = f2tf(base[0]);
                afr[mi][1] = f2tf(base[8 * AST]);
                afr[mi][2] = f2tf(base[4]);
                afr[mi][3] = f2tf(base[8 * AST + 4]);
            }
            const int bk = ks * 8 + (lane & 3);
            const int bn = lane >> 2;
#pragma unroll
            for (int ni = 0; ni < NI; ni++) {
                const float* base = &Bs[cur][bk * BST + wn + ni * 8 + bn];
                bfr[ni][0] = f2tf(base[0]);
                bfr[ni][1] = f2tf(base[4 * BST]);
            }
#pragma unroll
            for (int mi = 0; mi < MI; mi++)
#pragma unroll
                for (int ni = 0; ni < NI; ni++)
                    mma_tf32(acc[mi][ni], afr[mi], bfr[ni]);
        }
        __syncthreads();
    }

#pragma unroll
    for (int mi = 0; mi < MI; mi++) {
#pragma unroll
        for (int ni = 0; ni < NI; ni++) {
            const int r0 = row0 + wm + mi * 16 + (lane >> 2);
            const int c0 = col0 + wn + ni * 8 + 2 * (lane & 3);
#pragma unroll
            for (int half = 0; half < 2; half++) {
                const int rr = r0 + half * 8;
#pragma unroll
                for (int e = 0; e < 2; e++) {
                    const int nn = c0 + e;
                    float v = acc[mi][ni][half * 2 + e];
                    if (EPI == 1) {
                        v = tanhf(v + p0[nn]);
                        v = (v - p3[nn]) * rsqrtf(p4[nn] + BN_EPS) * p1[nn] + p2[nn];
                        v = tanhf(v);
                    } else if (EPI == 2) {
                        v += p0[nn];
                    }
                    C[(size_t)rr * N + nn] = v;
                }
            }
        }
    }
}

// ---------------- persistent LSTM recurrence ---------------------------------
// Grid = 128 CTAs (all co-resident on 148 SMs), 256 threads each.
// CTA (jt, mt): mt = blockIdx.x & 3 -> rows [mt*64, mt*64+64)
//               jt = blockIdx.x >> 2 -> hidden cols [jt*32, jt*32+32) x 4 gates
// Per step: 3-stage cp.async tf32 GEMM Zh = h_{t-1} @ Wr (K=1024), gates in
// epilogue, global h/c writes, then a grid-wide atomic barrier.
#define FBM 64
#define FBK 16
#define FBN 128              // 4 gate slabs x 32 j
#define FAST (FBK + 4)
#define FBST (FBN + 8)
#define FEST (FBN + 4)
#define PSTAGES 3

struct PSmem {
    union {
        struct {
            float As[PSTAGES][FBM * FAST];   // 15360 B
            float Bs[PSTAGES][FBK * FBST];   // 26112 B
        } mm;
        float ep[FBM * FEST];                // 33792 B
    };
};

__global__ void __launch_bounds__(256)
lstm_persistent(const float* __restrict__ Wr,      // (HH, 4*HH)
                const float* __restrict__ Zx,      // (BB*TT, 4*HH)
                float* __restrict__ cst,           // (BB, HH)
                float* __restrict__ hseq,          // (TT, BB, HH)
                const float* __restrict__ pi, const float* __restrict__ pf,
                const float* __restrict__ po)
{
    __shared__ PSmem S;

    const int tid  = threadIdx.x;
    const int lane = tid & 31;
    const int warp = tid >> 5;
    const int wm   = (warp >> 2) * 32;
    const int wn   = (warp & 3) * 32;
    const int row0 = (blockIdx.x & 3) * FBM;
    const int j0   = (blockIdx.x >> 2) * 32;

    const int j  = tid & 31;
    const int jg = j0 + j;
    const float pij = pi[jg], pfj = pf[jg], poj = po[jg];

    constexpr int BQ = FBK * FBN / 4;   // 512 float4 chunks per B tile
    constexpr int KT = HH / FBK;        // 64

#pragma unroll 1
    for (int t = 0; t < TT; t++) {
        float acc[2][4][4];
#pragma unroll
        for (int mi = 0; mi < 2; mi++)
#pragma unroll
            for (int ni = 0; ni < 4; ni++)
#pragma unroll
                for (int r = 0; r < 4; r++) acc[mi][ni][r] = 0.0f;

        if (t > 0) {
            const float* hprev = hseq + (size_t)(t - 1) * BB * HH;

            // ---- prologue: stage tiles 0 .. PSTAGES-2 ----
#pragma unroll
            for (int p = 0; p < PSTAGES - 1; p++) {
                const int k0 = p * FBK;
                {
                    int r = tid / (FBK/4), c = (tid % (FBK/4)) * 4;
                    cp16(&S.mm.As[p][r * FAST + c],
                         hprev + (size_t)(row0 + r) * HH + k0 + c);
                }
#pragma unroll
                for (int qq = tid; qq < BQ; qq += 256) {
                    int br = qq / 32, ci = qq % 32;
                    int g = ci >> 3, jj = (ci & 7) * 4;
                    cp16(&S.mm.Bs[p][br * FBST + g * 32 + jj],
                         Wr + (size_t)(k0 + br) * (4*HH) + g * HH + j0 + jj);
                }
                CP_COMMIT;
            }

#pragma unroll 1
            for (int kt = 0; kt < KT; kt++) {
                const int cur = kt % PSTAGES;
                CP_WAITN(PSTAGES - 2);     // tile kt resident
                __syncthreads();

                // issue tile kt + PSTAGES-1 into the buffer freed last iter
                if (kt + PSTAGES - 1 < KT) {
                    const int nxt = (kt + PSTAGES - 1) % PSTAGES;
                    const int k0 = (kt + PSTAGES - 1) * FBK;
                    {
                        int r = tid / (FBK/4), c = (tid % (FBK/4)) * 4;
                        cp16(&S.mm.As[nxt][r * FAST + c],
                             hprev + (size_t)(row0 + r) * HH + k0 + c);
                    }
#pragma unroll
                    for (int qq = tid; qq < BQ; qq += 256) {
                        int br = qq / 32, ci = qq % 32;
                        int g = ci >> 3, jj = (ci & 7) * 4;
                        cp16(&S.mm.Bs[nxt][br * FBST + g * 32 + jj],
                             Wr + (size_t)(k0 + br) * (4*HH) + g * HH + j0 + jj);
                    }
                }
                CP_COMMIT;

                // ---- compute tile kt ----
#pragma unroll
                for (int ks = 0; ks < FBK/8; ks++) {
                    uint32_t afr[2][4];
                    uint32_t bfr[4][2];
                    const int ar = lane >> 2;
                    const int ac = ks * 8 + (lane & 3);
#pragma unroll
                    for (int mi = 0; mi < 2; mi++) {
                        const float* base = &S.mm.As[cur][(wm + mi * 16 + ar) * FAST + ac];
                        afr[mi][0] = f2tf(base[0]);
                        afr[mi][1] = f2tf(base[8 * FAST]);
                        afr[mi][2] = f2tf(base[4]);
                        afr[mi][3] = f2tf(base[8 * FAST + 4]);
                    }
                    const int bk = ks * 8 + (lane & 3);
                    const int bn = lane >> 2;
#pragma unroll
                    for (int ni = 0; ni < 4; ni++) {
                        const float* base = &S.mm.Bs[cur][bk * FBST + wn + ni * 8 + bn];
                        bfr[ni][0] = f2tf(base[0]);
                        bfr[ni][1] = f2tf(base[4 * FBST]);
                    }
#pragma unroll
                    for (int mi = 0; mi < 2; mi++)
#pragma unroll
                        for (int ni = 0; ni < 4; ni++)
                            mma_tf32(acc[mi][ni], afr[mi], bfr[ni]);
                }
            }
            CP_WAITN(0);
        }
        __syncthreads();   // all mma smem reads done; smem free for epilogue

        // ---- dump Zh accumulators to smem epilogue buffer ----
#pragma unroll
        for (int mi = 0; mi < 2; mi++) {
#pragma unroll
            for (int ni = 0; ni < 4; ni++) {
                const int r0 = wm + mi * 16 + (lane >> 2);
                const int c0 = wn + ni * 8 + 2 * (lane & 3);
#pragma unroll
                for (int half = 0; half < 2; half++) {
                    S.ep[(r0 + half * 8) * FEST + c0]     = acc[mi][ni][half * 2];
                    S.ep[(r0 + half * 8) * FEST + c0 + 1] = acc[mi][ni][half * 2 + 1];
                }
            }
        }
        __syncthreads();

        // ---- gates: each thread handles 8 (m, j) pairs ----
        float* hout = hseq + (size_t)t * BB * HH;
#pragma unroll
        for (int s = 0; s < 8; s++) {
            const int m = s * 8 + (tid >> 5);
            const int b = row0 + m;
            const size_t zr = ((size_t)b * TT + t) * (4 * HH);

            float zi = S.ep[m * FEST +       j] + Zx[zr + 0*HH + jg];
            float zf = S.ep[m * FEST +  32 + j] + Zx[zr + 1*HH + jg];
            float zc = S.ep[m * FEST +  64 + j] + Zx[zr + 2*HH + jg];
            float zo = S.ep[m * FEST +  96 + j] + Zx[zr + 3*HH + jg];

            float cc = cst[(size_t)b * HH + jg];
            float ig = 1.0f / (1.0f + expf(-(zi + cc * pij)));
            float fg = 1.0f / (1.0f + expf(-(zf + cc * pfj)));
            float cn = fg * cc + ig * tanhf(zc);
            float og = 1.0f / (1.0f + expf(-(zo + cn * poj)));

            cst[(size_t)b * HH + jg]  = cn;
            hout[(size_t)b * HH + jg] = og * tanhf(cn);
        }

        // ---- grid barrier (release h_t to all CTAs) ----
        if (t + 1 < TT) {
            __threadfence();           // publish this thread's h/c stores
            __syncthreads();           // all threads of CTA published
            if (tid == 0) {
                atomicAdd((unsigned*)&g_bar, 1u);
                const unsigned target = 128u * (unsigned)(t + 1);
                while (g_bar < target) { }
                __threadfence();
            }
            __syncthreads();
        }
    }
}

// ---------------- final BN -> tanh -> Dense(H,10) ----------------------------
__global__ void logits_kernel(const float* __restrict__ hseq,
                              const float* __restrict__ g2, const float* __restrict__ b2,
                              const float* __restrict__ m2, const float* __restrict__ v2,
                              const float* __restrict__ Wout, float* __restrict__ out)
{
    int row = blockIdx.x;            // = t*BB + b (hseq is (T,B,H))
    int t = row / BB, b = row % BB;
    int tid = threadIdx.x;

    float a[CC];
#pragma unroll
    for (int c2 = 0; c2 < CC; c2++) a[c2] = 0.0f;

    float4 hv = *(const float4*)(hseq + (size_t)row * HH + tid * 4);
    float4 gv = *(const float4*)(g2 + tid * 4);
    float4 bv = *(const float4*)(b2 + tid * 4);
    float4 mv = *(const float4*)(m2 + tid * 4);
    float4 vv = *(const float4*)(v2 + tid * 4);

    float h4[4] = {hv.x, hv.y, hv.z, hv.w};
    float G4[4] = {gv.x, gv.y, gv.z, gv.w};
    float B4[4] = {bv.x, bv.y, bv.z, bv.w};
    float M4[4] = {mv.x, mv.y, mv.z, mv.w};
    float V4[4] = {vv.x, vv.y, vv.z, vv.w};

#pragma unroll
    for (int s = 0; s < 4; s++) {
        int k = tid * 4 + s;
        float y = tanhf((h4[s] - M4[s]) * rsqrtf(V4[s] + BN_EPS) * G4[s] + B4[s]);
        const float* wr = Wout + (size_t)k * CC;
#pragma unroll
        for (int c2 = 0; c2 < CC; c2++)
            a[c2] = fmaf(y, wr[c2], a[c2]);
    }

#pragma unroll
    for (int off = 16; off > 0; off >>= 1)
#pragma unroll
        for (int c2 = 0; c2 < CC; c2++)
            a[c2] += __shfl_down_sync(0xffffffffu, a[c2], off);

    __shared__ float sacc[CC];
    if (tid < CC) sacc[tid] = 0.0f;
    __syncthreads();
    if ((tid & 31) == 0)
#pragma unroll
        for (int c2 = 0; c2 < CC; c2++) atomicAdd(&sacc[c2], a[c2]);
    __syncthreads();
    if (tid < CC)
        out[((size_t)b * TT + t) * CC + tid] = sacc[tid];
}

// ---------------- launcher ----------------------------------------------------
extern "C" void kernel_launch(void* const* d_in, const int* in_sizes, int n_in,
                              void* d_out, int out_size)
{
    const float* x      = (const float*)d_in[0];
    const float* W_fe   = (const float*)d_in[1];
    const float* b_fe   = (const float*)d_in[2];
    const float* gamma1 = (const float*)d_in[3];
    const float* beta1  = (const float*)d_in[4];
    const float* mean1  = (const float*)d_in[5];
    const float* var1   = (const float*)d_in[6];
    const float* Wg     = (const float*)d_in[7];   // kernel (H, 4H)
    const float* Wr     = (const float*)d_in[8];   // rec_kernel (H, 4H)
    const float* bias   = (const float*)d_in[9];
    const float* pi     = (const float*)d_in[10];
    const float* pf     = (const float*)d_in[11];
    const float* po     = (const float*)d_in[12];
    const float* gamma2 = (const float*)d_in[13];
    const float* beta2  = (const float*)d_in[14];
    const float* mean2  = (const float*)d_in[15];
    const float* var2   = (const float*)d_in[16];
    const float* W_out  = (const float*)d_in[17];
    float* out = (float*)d_out;

    float *feat, *zx, *hseq, *cbuf;
    cudaGetSymbolAddress((void**)&feat, g_feat);
    cudaGetSymbolAddress((void**)&zx,   g_zx);
    cudaGetSymbolAddress((void**)&hseq, g_hseq);
    cudaGetSymbolAddress((void**)&cbuf, g_c);

    // zero cell state + grid-barrier counter (every replay)
    init_kernel<<<(BB*HH + 255)/256, 256>>>(cbuf, BB*HH);

    // 1) feat = tanh(BN(tanh(x @ W_fe + b_fe)))   [32768 x 1024, K=784]
    {
        dim3 grid(HH/128, M1/128);
        gemm_tf32<128,128,16,32,64,1><<<grid, 256>>>(
            x, W_fe, feat, M1, HH, FF, b_fe, gamma1, beta1, mean1, var1);
    }
    // 2) Zx = feat @ kernel + bias                [32768 x 4096, K=1024]
    {
        dim3 grid(4*HH/128, M1/128);
        gemm_tf32<128,128,16,32,64,2><<<grid, 256>>>(
            feat, Wg, zx, M1, 4*HH, HH, bias, nullptr, nullptr, nullptr, nullptr);
    }
    // 3) recurrence: single persistent kernel, grid barrier per step
    lstm_persistent<<<128, 256>>>(Wr, zx, cbuf, hseq, pi, pf, po);

    // 4) out = tanh(BN(hseq)) @ W_out             [32768 x 10]
    logits_kernel<<<M1, 256>>>(hseq, gamma2, beta2, mean2, var2, W_out, out);
}

// round 6
// speedup vs baseline: 1.2314x; 1.1868x over previous
#include <cuda_runtime.h>
#include <math.h>
#include <stdint.h>

// ---------------- problem constants ----------------
#define BB 256      // batch
#define TT 128      // timesteps
#define FF 784      // input features
#define HH 1024     // hidden
#define CC 10       // classes
#define M1 (BB*TT)  // 32768 rows for the time-parallel GEMMs
#define BN_EPS 1e-3f

// ---------------- scratch (device globals) ----------------
__device__ float g_feat[(size_t)M1 * HH];          // tf32-rounded feat
__device__ float g_zx  [(size_t)M1 * 4 * HH];      // fp32 Zx
__device__ float g_hseq[(size_t)M1 * HH];          // fp32 h (for logits)
__device__ float g_ht  [2][(size_t)BB * HH];       // tf32-rounded h ping-pong
__device__ float g_c   [(size_t)BB * HH];
__device__ float g_xr  [(size_t)M1 * FF];          // tf32-rounded x
__device__ float g_wfe [(size_t)FF * HH];          // tf32-rounded W_fe
__device__ float g_wg  [(size_t)HH * 4 * HH];      // tf32-rounded kernel
__device__ float g_wrt [(size_t)HH * 4 * HH];      // tf32-rounded rec_kernel
__device__ volatile unsigned g_bar;                // grid barrier counter

// ---------------- helpers ----------------
__device__ __forceinline__ uint32_t f2tf(float f) {
    uint32_t u;
    asm("cvt.rna.tf32.f32 %0, %1;" : "=r"(u) : "f"(f));
    return u;
}

__device__ __forceinline__ void cp16(void* dst, const void* src) {
    uint32_t d = (uint32_t)__cvta_generic_to_shared(dst);
    asm volatile("cp.async.cg.shared.global [%0], [%1], 16;" :: "r"(d), "l"(src));
}
#define CP_COMMIT asm volatile("cp.async.commit_group;")
#define CP_WAITN(n) asm volatile("cp.async.wait_group %0;" :: "n"(n))

__device__ __forceinline__ void mma_tf32(float* d, const uint32_t* a, const uint32_t* b) {
    asm volatile(
        "mma.sync.aligned.m16n8k8.row.col.f32.tf32.tf32.f32 "
        "{%0,%1,%2,%3}, {%4,%5,%6,%7}, {%8,%9}, {%0,%1,%2,%3};"
        : "+f"(d[0]), "+f"(d[1]), "+f"(d[2]), "+f"(d[3])
        : "r"(a[0]), "r"(a[1]), "r"(a[2]), "r"(a[3]),
          "r"(b[0]), "r"(b[1]));
}

__global__ void init_kernel(float* __restrict__ c, int n) {
    int i = blockIdx.x * blockDim.x + threadIdx.x;
    if (i < n) c[i] = 0.0f;
    if (i == 0) g_bar = 0u;
}

// pre-round an fp32 array to tf32 precision (rna), stored as fp32 bits
__global__ void round_tf32_kernel(const float4* __restrict__ in,
                                  float4* __restrict__ out, int n4) {
    int i = blockIdx.x * blockDim.x + threadIdx.x;
    if (i < n4) {
        float4 v = in[i];
        float4 o;
        o.x = __uint_as_float(f2tf(v.x));
        o.y = __uint_as_float(f2tf(v.y));
        o.z = __uint_as_float(f2tf(v.z));
        o.w = __uint_as_float(f2tf(v.w));
        out[i] = o;
    }
}

// ---------------- tf32 tensor-core GEMM (pre-rounded inputs) -----------------
// C[M,N] = epilogue(A[M,K] @ B[K,N]);  A,B already tf32-rounded.
// EPI 1: feat epilogue (tanh,BN,tanh), output stored tf32-rounded
// EPI 2: +bias, output fp32
template<int BM, int BN, int BK, int WM, int WN, int EPI>
__global__ void __launch_bounds__((BM/WM)*(BN/WN)*32)
gemm_tf32(const float* __restrict__ A, const float* __restrict__ B,
          float* __restrict__ C, int M, int N, int K,
          const float* __restrict__ p0, const float* __restrict__ p1,
          const float* __restrict__ p2, const float* __restrict__ p3,
          const float* __restrict__ p4)
{
    constexpr int WARPS_N = BN / WN;
    constexpr int THREADS = (BM/WM) * (BN/WN) * 32;
    constexpr int MI = WM / 16;
    constexpr int NI = WN / 8;
    constexpr int KS = BK / 8;
    constexpr int AST = BK + 4;
    constexpr int BST = BN + 8;
    constexpr int AQ = BM * BK / 4;
    constexpr int BQ = BK * BN / 4;

    __shared__ float As[2][BM * AST];
    __shared__ float Bs[2][BK * BST];

    const int tid  = threadIdx.x;
    const int lane = tid & 31;
    const int warp = tid >> 5;
    const int wm   = (warp / WARPS_N) * WM;
    const int wn   = (warp % WARPS_N) * WN;
    const int row0 = blockIdx.y * BM;
    const int col0 = blockIdx.x * BN;

    float acc[MI][NI][4];
#pragma unroll
    for (int mi = 0; mi < MI; mi++)
#pragma unroll
        for (int ni = 0; ni < NI; ni++)
#pragma unroll
            for (int r = 0; r < 4; r++) acc[mi][ni][r] = 0.0f;

    const int KT = K / BK;

#pragma unroll
    for (int q = tid; q < AQ; q += THREADS) {
        int r = q / (BK/4), c = (q % (BK/4)) * 4;
        cp16(&As[0][r * AST + c], A + (size_t)(row0 + r) * K + c);
    }
#pragma unroll
    for (int q = tid; q < BQ; q += THREADS) {
        int r = q / (BN/4), c = (q % (BN/4)) * 4;
        cp16(&Bs[0][r * BST + c], B + (size_t)r * N + col0 + c);
    }
    CP_COMMIT;

#pragma unroll 1
    for (int kt = 0; kt < KT; kt++) {
        const int cur = kt & 1;
        if (kt + 1 < KT) {
            const int k0 = (kt + 1) * BK;
            const int nxt = cur ^ 1;
#pragma unroll
            for (int q = tid; q < AQ; q += THREADS) {
                int r = q / (BK/4), c = (q % (BK/4)) * 4;
                cp16(&As[nxt][r * AST + c], A + (size_t)(row0 + r) * K + k0 + c);
            }
#pragma unroll
            for (int q = tid; q < BQ; q += THREADS) {
                int r = q / (BN/4), c = (q % (BN/4)) * 4;
                cp16(&Bs[nxt][r * BST + c], B + (size_t)(k0 + r) * N + col0 + c);
            }
            CP_COMMIT;
            CP_WAITN(1);
        } else {
            CP_WAITN(0);
        }
        __syncthreads();

#pragma unroll
        for (int ks = 0; ks < KS; ks++) {
            uint32_t afr[MI][4];
            uint32_t bfr[NI][2];
            const int ar = lane >> 2;
            const int ac = ks * 8 + (lane & 3);
#pragma unroll
            for (int mi = 0; mi < MI; mi++) {
                const float* base = &As[cur][(wm + mi * 16 + ar) * AST + ac];
                afr[mi][0] = __float_as_uint(base[0]);
                afr[mi][1] = __float_as_uint(base[8 * AST]);
                afr[mi][2] = __float_as_uint(base[4]);
                afr[mi][3] = __float_as_uint(base[8 * AST + 4]);
            }
            const int bk = ks * 8 + (lane & 3);
            const int bn = lane >> 2;
#pragma unroll
            for (int ni = 0; ni < NI; ni++) {
                const float* base = &Bs[cur][bk * BST + wn + ni * 8 + bn];
                bfr[ni][0] = __float_as_uint(base[0]);
                bfr[ni][1] = __float_as_uint(base[4 * BST]);
            }
#pragma unroll
            for (int mi = 0; mi < MI; mi++)
#pragma unroll
                for (int ni = 0; ni < NI; ni++)
                    mma_tf32(acc[mi][ni], afr[mi], bfr[ni]);
        }
        __syncthreads();
    }

#pragma unroll
    for (int mi = 0; mi < MI; mi++) {
#pragma unroll
        for (int ni = 0; ni < NI; ni++) {
            const int r0 = row0 + wm + mi * 16 + (lane >> 2);
            const int c0 = col0 + wn + ni * 8 + 2 * (lane & 3);
#pragma unroll
            for (int half = 0; half < 2; half++) {
                const int rr = r0 + half * 8;
#pragma unroll
                for (int e = 0; e < 2; e++) {
                    const int nn = c0 + e;
                    float v = acc[mi][ni][half * 2 + e];
                    if (EPI == 1) {
                        v = tanhf(v + p0[nn]);
                        v = (v - p3[nn]) * rsqrtf(p4[nn] + BN_EPS) * p1[nn] + p2[nn];
                        v = tanhf(v);
                        v = __uint_as_float(f2tf(v));   // pre-round for GEMM2
                    } else if (EPI == 2) {
                        v += p0[nn];
                    }
                    C[(size_t)rr * N + nn] = v;
                }
            }
        }
    }
}

// ---------------- persistent LSTM recurrence ---------------------------------
// 128 CTAs, 256 threads; CTA (jt, mt). Per step: 3-stage cp.async tf32 GEMM
// Zh = h_{t-1} @ Wr (K=1024, FBK=32), gates in epilogue, grid barrier.
// All MMA operands pre-rounded to tf32 -> no cvt in the loop.
#define FBM 64
#define FBK 32
#define FBN 128
#define FAST (FBK + 4)       // 36
#define FBST (FBN + 8)       // 136
#define FEST (FBN + 4)       // 132
#define PSTAGES 3
#define AS_SZ (FBM * FAST)   // 2304 floats
#define BS_SZ (FBK * FBST)   // 4352 floats
#define PSMEM_BYTES ((PSTAGES * (AS_SZ + BS_SZ)) * 4)   // 79872 B

__global__ void __launch_bounds__(256)
lstm_persistent(const float* __restrict__ Wr,      // tf32-rounded (HH, 4*HH)
                const float* __restrict__ Zx,      // (BB*TT, 4*HH)
                float* __restrict__ cst,           // (BB, HH)
                float* __restrict__ hseq,          // (TT, BB, HH) fp32
                float* __restrict__ ht0,           // ping-pong tf32 h buffers
                float* __restrict__ ht1,
                const float* __restrict__ pi, const float* __restrict__ pf,
                const float* __restrict__ po)
{
    extern __shared__ float dsm[];
    float* As = dsm;                          // [PSTAGES][AS_SZ]
    float* Bs = dsm + PSTAGES * AS_SZ;        // [PSTAGES][BS_SZ]
    float* ep = dsm;                          // epilogue alias (33792 B)

    const int tid  = threadIdx.x;
    const int lane = tid & 31;
    const int warp = tid >> 5;
    const int wm   = (warp >> 2) * 32;
    const int wn   = (warp & 3) * 32;
    const int row0 = (blockIdx.x & 3) * FBM;
    const int j0   = (blockIdx.x >> 2) * 32;

    const int j  = tid & 31;
    const int jg = j0 + j;
    const float pij = pi[jg], pfj = pf[jg], poj = po[jg];

    constexpr int AQ = FBM * FBK / 4;   // 512
    constexpr int BQ = FBK * FBN / 4;   // 1024
    constexpr int KT = HH / FBK;        // 32

#pragma unroll 1
    for (int t = 0; t < TT; t++) {
        float acc[2][4][4];
#pragma unroll
        for (int mi = 0; mi < 2; mi++)
#pragma unroll
            for (int ni = 0; ni < 4; ni++)
#pragma unroll
                for (int r = 0; r < 4; r++) acc[mi][ni][r] = 0.0f;

        if (t > 0) {
            const float* hprev = ((t - 1) & 1) ? ht1 : ht0;

#pragma unroll
            for (int p = 0; p < PSTAGES - 1; p++) {
                const int k0 = p * FBK;
#pragma unroll
                for (int qq = tid; qq < AQ; qq += 256) {
                    int r = qq / (FBK/4), c = (qq % (FBK/4)) * 4;
                    cp16(&As[p * AS_SZ + r * FAST + c],
                         hprev + (size_t)(row0 + r) * HH + k0 + c);
                }
#pragma unroll
                for (int qq = tid; qq < BQ; qq += 256) {
                    int br = qq / 32, ci = qq % 32;
                    int g = ci >> 3, jj = (ci & 7) * 4;
                    cp16(&Bs[p * BS_SZ + br * FBST + g * 32 + jj],
                         Wr + (size_t)(k0 + br) * (4*HH) + g * HH + j0 + jj);
                }
                CP_COMMIT;
            }

#pragma unroll 1
            for (int kt = 0; kt < KT; kt++) {
                const int cur = kt % PSTAGES;
                CP_WAITN(PSTAGES - 2);
                __syncthreads();

                if (kt + PSTAGES - 1 < KT) {
                    const int nxt = (kt + PSTAGES - 1) % PSTAGES;
                    const int k0 = (kt + PSTAGES - 1) * FBK;
#pragma unroll
                    for (int qq = tid; qq < AQ; qq += 256) {
                        int r = qq / (FBK/4), c = (qq % (FBK/4)) * 4;
                        cp16(&As[nxt * AS_SZ + r * FAST + c],
                             hprev + (size_t)(row0 + r) * HH + k0 + c);
                    }
#pragma unroll
                    for (int qq = tid; qq < BQ; qq += 256) {
                        int br = qq / 32, ci = qq % 32;
                        int g = ci >> 3, jj = (ci & 7) * 4;
                        cp16(&Bs[nxt * BS_SZ + br * FBST + g * 32 + jj],
                             Wr + (size_t)(k0 + br) * (4*HH) + g * HH + j0 + jj);
                    }
                }
                CP_COMMIT;

#pragma unroll
                for (int ks = 0; ks < FBK/8; ks++) {
                    uint32_t afr[2][4];
                    uint32_t bfr[4][2];
                    const int ar = lane >> 2;
                    const int ac = ks * 8 + (lane & 3);
#pragma unroll
                    for (int mi = 0; mi < 2; mi++) {
                        const float* base = &As[cur * AS_SZ + (wm + mi * 16 + ar) * FAST + ac];
                        afr[mi][0] = __float_as_uint(base[0]);
                        afr[mi][1] = __float_as_uint(base[8 * FAST]);
                        afr[mi][2] = __float_as_uint(base[4]);
                        afr[mi][3] = __float_as_uint(base[8 * FAST + 4]);
                    }
                    const int bk = ks * 8 + (lane & 3);
                    const int bn = lane >> 2;
#pragma unroll
                    for (int ni = 0; ni < 4; ni++) {
                        const float* base = &Bs[cur * BS_SZ + bk * FBST + wn + ni * 8 + bn];
                        bfr[ni][0] = __float_as_uint(base[0]);
                        bfr[ni][1] = __float_as_uint(base[4 * FBST]);
                    }
#pragma unroll
                    for (int mi = 0; mi < 2; mi++)
#pragma unroll
                        for (int ni = 0; ni < 4; ni++)
                            mma_tf32(acc[mi][ni], afr[mi], bfr[ni]);
                }
            }
            CP_WAITN(0);
        }
        __syncthreads();

        // ---- dump Zh accumulators to smem epilogue buffer ----
#pragma unroll
        for (int mi = 0; mi < 2; mi++) {
#pragma unroll
            for (int ni = 0; ni < 4; ni++) {
                const int r0 = wm + mi * 16 + (lane >> 2);
                const int c0 = wn + ni * 8 + 2 * (lane & 3);
#pragma unroll
                for (int half = 0; half < 2; half++) {
                    ep[(r0 + half * 8) * FEST + c0]     = acc[mi][ni][half * 2];
                    ep[(r0 + half * 8) * FEST + c0 + 1] = acc[mi][ni][half * 2 + 1];
                }
            }
        }
        __syncthreads();

        // ---- gates ----
        float* hout  = hseq + (size_t)t * BB * HH;
        float* htcur = (t & 1) ? ht1 : ht0;
#pragma unroll
        for (int s = 0; s < 8; s++) {
            const int m = s * 8 + (tid >> 5);
            const int b = row0 + m;
            const size_t zr = ((size_t)b * TT + t) * (4 * HH);

            float zi = ep[m * FEST +       j] + Zx[zr + 0*HH + jg];
            float zf = ep[m * FEST +  32 + j] + Zx[zr + 1*HH + jg];
            float zc = ep[m * FEST +  64 + j] + Zx[zr + 2*HH + jg];
            float zo = ep[m * FEST +  96 + j] + Zx[zr + 3*HH + jg];

            float cc = cst[(size_t)b * HH + jg];
            float ig = 1.0f / (1.0f + expf(-(zi + cc * pij)));
            float fg = 1.0f / (1.0f + expf(-(zf + cc * pfj)));
            float cn = fg * cc + ig * tanhf(zc);
            float og = 1.0f / (1.0f + expf(-(zo + cn * poj)));
            float hn = og * tanhf(cn);

            cst[(size_t)b * HH + jg]   = cn;
            hout[(size_t)b * HH + jg]  = hn;
            htcur[(size_t)b * HH + jg] = __uint_as_float(f2tf(hn));
        }

        // ---- grid barrier ----
        if (t + 1 < TT) {
            __threadfence();
            __syncthreads();
            if (tid == 0) {
                atomicAdd((unsigned*)&g_bar, 1u);
                const unsigned target = 128u * (unsigned)(t + 1);
                while (g_bar < target) { }
                __threadfence();
            }
            __syncthreads();
        }
    }
}

// ---------------- final BN -> tanh -> Dense(H,10) ----------------------------
__global__ void logits_kernel(const float* __restrict__ hseq,
                              const float* __restrict__ g2, const float* __restrict__ b2,
                              const float* __restrict__ m2, const float* __restrict__ v2,
                              const float* __restrict__ Wout, float* __restrict__ out)
{
    int row = blockIdx.x;            // = t*BB + b (hseq is (T,B,H))
    int t = row / BB, b = row % BB;
    int tid = threadIdx.x;

    float a[CC];
#pragma unroll
    for (int c2 = 0; c2 < CC; c2++) a[c2] = 0.0f;

    float4 hv = *(const float4*)(hseq + (size_t)row * HH + tid * 4);
    float4 gv = *(const float4*)(g2 + tid * 4);
    float4 bv = *(const float4*)(b2 + tid * 4);
    float4 mv = *(const float4*)(m2 + tid * 4);
    float4 vv = *(const float4*)(v2 + tid * 4);

    float h4[4] = {hv.x, hv.y, hv.z, hv.w};
    float G4[4] = {gv.x, gv.y, gv.z, gv.w};
    float B4[4] = {bv.x, bv.y, bv.z, bv.w};
    float M4[4] = {mv.x, mv.y, mv.z, mv.w};
    float V4[4] = {vv.x, vv.y, vv.z, vv.w};

#pragma unroll
    for (int s = 0; s < 4; s++) {
        int k = tid * 4 + s;
        float y = tanhf((h4[s] - M4[s]) * rsqrtf(V4[s] + BN_EPS) * G4[s] + B4[s]);
        const float* wr = Wout + (size_t)k * CC;
#pragma unroll
        for (int c2 = 0; c2 < CC; c2++)
            a[c2] = fmaf(y, wr[c2], a[c2]);
    }

#pragma unroll
    for (int off = 16; off > 0; off >>= 1)
#pragma unroll
        for (int c2 = 0; c2 < CC; c2++)
            a[c2] += __shfl_down_sync(0xffffffffu, a[c2], off);

    __shared__ float sacc[CC];
    if (tid < CC) sacc[tid] = 0.0f;
    __syncthreads();
    if ((tid & 31) == 0)
#pragma unroll
        for (int c2 = 0; c2 < CC; c2++) atomicAdd(&sacc[c2], a[c2]);
    __syncthreads();
    if (tid < CC)
        out[((size_t)b * TT + t) * CC + tid] = sacc[tid];
}

// ---------------- launcher ----------------------------------------------------
extern "C" void kernel_launch(void* const* d_in, const int* in_sizes, int n_in,
                              void* d_out, int out_size)
{
    const float* x      = (const float*)d_in[0];
    const float* W_fe   = (const float*)d_in[1];
    const float* b_fe   = (const float*)d_in[2];
    const float* gamma1 = (const float*)d_in[3];
    const float* beta1  = (const float*)d_in[4];
    const float* mean1  = (const float*)d_in[5];
    const float* var1   = (const float*)d_in[6];
    const float* Wg     = (const float*)d_in[7];
    const float* Wr     = (const float*)d_in[8];
    const float* bias   = (const float*)d_in[9];
    const float* pi     = (const float*)d_in[10];
    const float* pf     = (const float*)d_in[11];
    const float* po     = (const float*)d_in[12];
    const float* gamma2 = (const float*)d_in[13];
    const float* beta2  = (const float*)d_in[14];
    const float* mean2  = (const float*)d_in[15];
    const float* var2   = (const float*)d_in[16];
    const float* W_out  = (const float*)d_in[17];
    float* out = (float*)d_out;

    float *feat, *zx, *hseq, *cbuf, *xr, *wfe, *wg, *wrt, *ht;
    cudaGetSymbolAddress((void**)&feat, g_feat);
    cudaGetSymbolAddress((void**)&zx,   g_zx);
    cudaGetSymbolAddress((void**)&hseq, g_hseq);
    cudaGetSymbolAddress((void**)&cbuf, g_c);
    cudaGetSymbolAddress((void**)&xr,   g_xr);
    cudaGetSymbolAddress((void**)&wfe,  g_wfe);
    cudaGetSymbolAddress((void**)&wg,   g_wg);
    cudaGetSymbolAddress((void**)&wrt,  g_wrt);
    cudaGetSymbolAddress((void**)&ht,   g_ht);
    float* ht0 = ht;
    float* ht1 = ht + (size_t)BB * HH;

    cudaFuncSetAttribute(lstm_persistent,
                         cudaFuncAttributeMaxDynamicSharedMemorySize, PSMEM_BYTES);

    // init cell state + barrier
    init_kernel<<<(BB*HH + 255)/256, 256>>>(cbuf, BB*HH);

    // pre-round operands to tf32 (rna), stored as fp32
    {
        int n;
        n = M1*FF/4;      round_tf32_kernel<<<(n+255)/256,256>>>((const float4*)x,   (float4*)xr,  n);
        n = FF*HH/4;      round_tf32_kernel<<<(n+255)/256,256>>>((const float4*)W_fe,(float4*)wfe, n);
        n = HH*4*HH/4;    round_tf32_kernel<<<(n+255)/256,256>>>((const float4*)Wg,  (float4*)wg,  n);
        n = HH*4*HH/4;    round_tf32_kernel<<<(n+255)/256,256>>>((const float4*)Wr,  (float4*)wrt, n);
    }

    // 1) feat = tanh(BN(tanh(x @ W_fe + b_fe)))   [32768 x 1024, K=784]
    {
        dim3 grid(HH/128, M1/128);
        gemm_tf32<128,128,16,32,64,1><<<grid, 256>>>(
            xr, wfe, feat, M1, HH, FF, b_fe, gamma1, beta1, mean1, var1);
    }
    // 2) Zx = feat @ kernel + bias                [32768 x 4096, K=1024]
    {
        dim3 grid(4*HH/128, M1/128);
        gemm_tf32<128,128,16,32,64,2><<<grid, 256>>>(
            feat, wg, zx, M1, 4*HH, HH, bias, nullptr, nullptr, nullptr, nullptr);
    }
    // 3) recurrence: persistent kernel, grid barrier per step
    lstm_persistent<<<128, 256, PSMEM_BYTES>>>(wrt, zx, cbuf, hseq, ht0, ht1,
                                               pi, pf, po);

    // 4) out = tanh(BN(hseq)) @ W_out             [32768 x 10]
    logits_kernel<<<M1, 256>>>(hseq, gamma2, beta2, mean2, var2, W_out, out);
}